// round 1
// baseline (speedup 1.0000x reference)
#include <cuda_runtime.h>

// Problem constants
// B=64, N=1000, D=512, H=8, S=20, DK=64
#define NEG_BIG (-1e9f)
#define INV_SQRT_DK 0.125f
#define INV_SQRT_D 0.04419417382415922f   // 1/sqrt(512)

// ---------------- device scratch (static globals: allocation-free) ----------------
__device__ __align__(16) float g_kvl[64000 * 1536];      // [b*1000+n][ gk(512) | gv(512) | lk(512) ]
__device__ __align__(16) float g_heads[1280 * 512];      // [b*20+s][h*64+dk]
__device__ __align__(16) float g_glimpse[1280 * 512];    // [b*20+s][d]
__device__ __align__(16) float g_logits[1280 * 1000];    // [b*20+s][n]
__device__ int g_mask_mode;                              // 1 = 4-byte words (int32/float32), 0 = bytes

// ---------------- helpers ----------------
__device__ __forceinline__ float2 ffma2(float2 a, float2 b, float2 c) {
    unsigned long long ua = *reinterpret_cast<unsigned long long*>(&a);
    unsigned long long ub = *reinterpret_cast<unsigned long long*>(&b);
    unsigned long long uc = *reinterpret_cast<unsigned long long*>(&c);
    unsigned long long ud;
    asm("fma.rn.f32x2 %0, %1, %2, %3;" : "=l"(ud) : "l"(ua), "l"(ub), "l"(uc));
    return *reinterpret_cast<float2*>(&ud);
}

__device__ __forceinline__ bool is_feasible(const void* mp, int idx, int mode) {
    if (mode) return ((const unsigned int*)mp)[idx] != 0u;
    return ((const unsigned char*)mp)[idx] != 0;
}

__device__ __forceinline__ float warp_max(float v) {
#pragma unroll
    for (int o = 16; o; o >>= 1) v = fmaxf(v, __shfl_xor_sync(0xffffffffu, v, o));
    return v;
}
__device__ __forceinline__ float warp_sum(float v) {
#pragma unroll
    for (int o = 16; o; o >>= 1) v += __shfl_xor_sync(0xffffffffu, v, o);
    return v;
}

// ---------------- mask dtype sniffer ----------------
__global__ void detect_mask_kernel(const unsigned int* mw) {
    __shared__ int notI32, notF32;
    if (threadIdx.x == 0) { notI32 = 0; notF32 = 0; }
    __syncthreads();
    int ni = 0, nf = 0;
    for (int i = threadIdx.x; i < 1024; i += 256) {
        unsigned int v = mw[i];
        if (v != 0u && v != 1u) ni = 1;
        if (v != 0u && v != 0x3F800000u) nf = 1;
    }
    if (ni) atomicOr(&notI32, 1);
    if (nf) atomicOr(&notF32, 1);
    __syncthreads();
    if (threadIdx.x == 0) {
        // if every sampled 32-bit word matches an int32{0,1} or float32{0,1} pattern,
        // the mask is 4 bytes/element; otherwise it's a byte array (bool/int8).
        g_mask_mode = (notI32 && notF32) ? 0 : 1;
    }
}

// ---------------- fp32 GEMM: C[M,Nn] = A[M,K] @ B[K,Nn], all row-major ----------------
// 128x128 block tile, BK=16, 8x8 per thread, packed f32x2 FMA, double-buffered smem.
// Requires M%128==0, Nn%128==0, K%16==0.
__global__ __launch_bounds__(256, 2)
void gemm_f32(const float* __restrict__ A, const float* __restrict__ Bm,
              float* __restrict__ C, int M, int Nn, int K)
{
    __shared__ __align__(16) float As[2][16][128];
    __shared__ __align__(16) float Bs[2][16][128];
    const int tid = threadIdx.x;
    const int bm = blockIdx.y * 128;
    const int bn = blockIdx.x * 128;
    const int ar = tid >> 2;            // 0..63
    const int ac = (tid & 3) << 2;      // 0,4,8,12
    const int br = tid >> 5;            // 0..7
    const int bc = (tid & 31) << 2;     // 0..124
    const int ty = tid >> 4;            // 0..15
    const int tx = tid & 15;            // 0..15

    const float* Ab  = A + (size_t)(bm + ar) * K + ac;
    const float* Ab2 = A + (size_t)(bm + ar + 64) * K + ac;
    const float* Bb  = Bm + (size_t)br * Nn + bn + bc;
    const float* Bb2 = Bm + (size_t)(br + 8) * Nn + bn + bc;

    float2 acc[8][4];
#pragma unroll
    for (int i = 0; i < 8; i++)
#pragma unroll
        for (int j = 0; j < 4; j++) acc[i][j] = make_float2(0.f, 0.f);

    // prologue: tile 0
    {
        float4 a0 = *(const float4*)(Ab);
        float4 a1 = *(const float4*)(Ab2);
        float4 b0 = *(const float4*)(Bb);
        float4 b1 = *(const float4*)(Bb2);
        As[0][ac + 0][ar] = a0.x; As[0][ac + 1][ar] = a0.y;
        As[0][ac + 2][ar] = a0.z; As[0][ac + 3][ar] = a0.w;
        As[0][ac + 0][ar + 64] = a1.x; As[0][ac + 1][ar + 64] = a1.y;
        As[0][ac + 2][ar + 64] = a1.z; As[0][ac + 3][ar + 64] = a1.w;
        *(float4*)&Bs[0][br][bc] = b0;
        *(float4*)&Bs[0][br + 8][bc] = b1;
    }
    __syncthreads();

    const int nkt = K >> 4;
    for (int kt = 0; kt < nkt; ++kt) {
        const int cur = kt & 1, nxt = cur ^ 1;
        float4 a0, a1, b0, b1;
        const bool more = (kt + 1 < nkt);
        if (more) {
            const int ko = (kt + 1) << 4;
            a0 = *(const float4*)(Ab + ko);
            a1 = *(const float4*)(Ab2 + ko);
            b0 = *(const float4*)(Bb + (size_t)ko * Nn);
            b1 = *(const float4*)(Bb2 + (size_t)ko * Nn);
        }
#pragma unroll
        for (int k = 0; k < 16; ++k) {
            float4 af0 = *(const float4*)&As[cur][k][ty * 8];
            float4 af1 = *(const float4*)&As[cur][k][ty * 8 + 4];
            float4 bf0 = *(const float4*)&Bs[cur][k][tx * 8];
            float4 bf1 = *(const float4*)&Bs[cur][k][tx * 8 + 4];
            float av[8] = {af0.x, af0.y, af0.z, af0.w, af1.x, af1.y, af1.z, af1.w};
            float2 bv[4] = {make_float2(bf0.x, bf0.y), make_float2(bf0.z, bf0.w),
                            make_float2(bf1.x, bf1.y), make_float2(bf1.z, bf1.w)};
#pragma unroll
            for (int i = 0; i < 8; ++i) {
                float2 ap = make_float2(av[i], av[i]);
#pragma unroll
                for (int j = 0; j < 4; ++j)
                    acc[i][j] = ffma2(ap, bv[j], acc[i][j]);
            }
        }
        if (more) {
            As[nxt][ac + 0][ar] = a0.x; As[nxt][ac + 1][ar] = a0.y;
            As[nxt][ac + 2][ar] = a0.z; As[nxt][ac + 3][ar] = a0.w;
            As[nxt][ac + 0][ar + 64] = a1.x; As[nxt][ac + 1][ar + 64] = a1.y;
            As[nxt][ac + 2][ar + 64] = a1.z; As[nxt][ac + 3][ar + 64] = a1.w;
            *(float4*)&Bs[nxt][br][bc] = b0;
            *(float4*)&Bs[nxt][br + 8][bc] = b1;
        }
        __syncthreads();
    }

    float* Cp = C + (size_t)(bm + ty * 8) * Nn + bn + tx * 8;
#pragma unroll
    for (int i = 0; i < 8; ++i) {
        float4 v0 = make_float4(acc[i][0].x, acc[i][0].y, acc[i][1].x, acc[i][1].y);
        float4 v1 = make_float4(acc[i][2].x, acc[i][2].y, acc[i][3].x, acc[i][3].y);
        *(float4*)(Cp + (size_t)i * Nn) = v0;
        *(float4*)(Cp + (size_t)i * Nn + 4) = v1;
    }
}

// ---------------- flash-style masked MHA: heads[b,s,h*64+dk] ----------------
// grid (H=8, B=64), block 640 threads (warp w<20 owns query s=w).
__global__ __launch_bounds__(640)
void attn_kernel(const float* __restrict__ qin, const void* __restrict__ mask)
{
    __shared__ __align__(16) float sq[20][64];
    __shared__ __align__(16) float sk[40][64];
    __shared__ __align__(16) float sv[40][64];
    const int h = blockIdx.x, b = blockIdx.y;
    const int tid = threadIdx.x;
    const int mode = g_mask_mode;

    if (tid < 320) {
        int s = tid >> 4, dg = (tid & 15) << 2;
        *(float4*)&sq[s][dg] = *(const float4*)(qin + (size_t)(b * 20 + s) * 512 + h * 64 + dg);
    }

    const int lane = tid & 31, w = tid >> 5;
    float m = -1e30f, l = 0.f, acc0 = 0.f, acc1 = 0.f;
    float q0 = 0.f, q1 = 0.f;

    const int nn = tid >> 4;              // 0..39
    const int dg = (tid & 15) << 2;       // 0..60

    for (int t = 0; t < 25; ++t) {
        const int n0 = t * 40;
        __syncthreads();   // previous tile fully consumed
        {
            const float* base = g_kvl + (size_t)(b * 1000 + n0 + nn) * 1536 + h * 64 + dg;
            *(float4*)&sk[nn][dg] = *(const float4*)(base);
            *(float4*)&sv[nn][dg] = *(const float4*)(base + 512);
        }
        __syncthreads();
        if (w < 20) {
            if (t == 0) { q0 = sq[w][lane]; q1 = sq[w][lane + 32]; }
            const int midx0 = (b * 20 + w) * 1000 + n0;
#pragma unroll 4
            for (int n = 0; n < 40; ++n) {
                float x = q0 * sk[n][lane] + q1 * sk[n][lane + 32];
                x += __shfl_xor_sync(0xffffffffu, x, 16);
                x += __shfl_xor_sync(0xffffffffu, x, 8);
                x += __shfl_xor_sync(0xffffffffu, x, 4);
                x += __shfl_xor_sync(0xffffffffu, x, 2);
                x += __shfl_xor_sync(0xffffffffu, x, 1);
                x *= INV_SQRT_DK;
                if (is_feasible(mask, midx0 + n, mode)) {
                    float mn = fmaxf(m, x);
                    float corr = __expf(m - mn);
                    float p = __expf(x - mn);
                    l = l * corr + p;
                    acc0 = acc0 * corr + p * sv[n][lane];
                    acc1 = acc1 * corr + p * sv[n][lane + 32];
                    m = mn;
                }
            }
        }
    }
    if (w < 20) {
        float inv = 1.f / l;
        size_t o = (size_t)(b * 20 + w) * 512 + h * 64 + lane;
        g_heads[o] = acc0 * inv;
        g_heads[o + 32] = acc1 * inv;
    }
}

// ---------------- pointer logits: logits[b,s,n] = mask(10*tanh(g.lk/sqrt(D))) ----------------
// grid (B=64, 2 s-halves, 5 n-slices of 200), block 256.
__global__ __launch_bounds__(256)
void pointer_kernel(const void* __restrict__ mask)
{
    __shared__ __align__(16) float sg[10 * 512];   // 20 KB
    __shared__ __align__(16) float slk[8 * 512];   // 16 KB
    const int b = blockIdx.x;
    const int sbase = blockIdx.y * 10;
    const int nsl = blockIdx.z;
    const int tid = threadIdx.x;
    const int mode = g_mask_mode;

    for (int i = tid; i < 10 * 512 / 4; i += 256) {
        int off = i << 2;
        int s = off >> 9, d = off & 511;
        *(float4*)&sg[off] = *(const float4*)(g_glimpse + (size_t)(b * 20 + sbase + s) * 512 + d);
    }

    const int lane = tid & 31, w = tid >> 5;
    for (int t = 0; t < 25; ++t) {
        const int n0 = nsl * 200 + t * 8;
        __syncthreads();
        for (int i = tid; i < 8 * 512 / 4; i += 256) {
            int off = i << 2;
            int nn = off >> 9, d = off & 511;
            *(float4*)&slk[off] = *(const float4*)(g_kvl + (size_t)(b * 1000 + n0 + nn) * 1536 + 1024 + d);
        }
        __syncthreads();
#pragma unroll
        for (int pp = 0; pp < 10; ++pp) {
            const int p = w * 10 + pp;
            const int sl = p >> 3, n = p & 7;
            const float* gr = &sg[sl * 512];
            const float* kr = &slk[n * 512];
            float sum = 0.f;
#pragma unroll
            for (int i = 0; i < 16; ++i)
                sum += gr[lane + i * 32] * kr[lane + i * 32];
            sum = warp_sum(sum);
            if (lane == 0) {
                float lg = 10.f * tanhf(sum * INV_SQRT_D);
                int gidx = (b * 20 + sbase + sl) * 1000 + n0 + n;
                if (!is_feasible(mask, gidx, mode)) lg = NEG_BIG;
                g_logits[gidx] = lg;
            }
        }
    }
}

// ---------------- log-softmax over n, write transposed output ----------------
// grid (S=20, B=64), block 256. out[(s*64+b)*1000 + n]
__global__ __launch_bounds__(256)
void lsm_kernel(float* __restrict__ out)
{
    const int s = blockIdx.x, b = blockIdx.y;
    const float* row = g_logits + (size_t)(b * 20 + s) * 1000;
    float* orow = out + (size_t)(s * 64 + b) * 1000;
    __shared__ float red[8];
    const int tid = threadIdx.x;
    const int lane = tid & 31, w = tid >> 5;

    float mx = -1e30f;
    for (int i = tid; i < 1000; i += 256) mx = fmaxf(mx, row[i]);
    mx = warp_max(mx);
    if (lane == 0) red[w] = mx;
    __syncthreads();
    if (w == 0) {
        float v = (lane < 8) ? red[lane] : -1e30f;
        v = warp_max(v);
        if (lane == 0) red[0] = v;
    }
    __syncthreads();
    mx = red[0];
    __syncthreads();

    float se = 0.f;
    for (int i = tid; i < 1000; i += 256) se += __expf(row[i] - mx);
    se = warp_sum(se);
    if (lane == 0) red[w] = se;
    __syncthreads();
    if (w == 0) {
        float v = (lane < 8) ? red[lane] : 0.f;
        v = warp_sum(v);
        if (lane == 0) red[0] = v;
    }
    __syncthreads();
    const float lse = mx + logf(red[0]);

    for (int i = tid; i < 1000; i += 256) orow[i] = row[i] - lse;
}

// ---------------- launch ----------------
extern "C" void kernel_launch(void* const* d_in, const int* in_sizes, int n_in,
                              void* d_out, int out_size)
{
    (void)out_size;
    // Map inputs by element count (all distinct) to be robust to ordering.
    const float* emb = nullptr;   // 64*1000*512 = 32768000
    const float* q = nullptr;     // 64*20*512   = 655360
    const void* mask = nullptr;   // 64*20*1000  = 1280000
    const float* Wkvl = nullptr;  // 512*1536    = 786432
    const float* Wout = nullptr;  // 512*512     = 262144
    for (int i = 0; i < n_in; ++i) {
        switch (in_sizes[i]) {
            case 32768000: emb = (const float*)d_in[i]; break;
            case 655360:   q = (const float*)d_in[i]; break;
            case 1280000:  mask = d_in[i]; break;
            case 786432:   Wkvl = (const float*)d_in[i]; break;
            case 262144:   Wout = (const float*)d_in[i]; break;
            default: break;
        }
    }
    float* out = (float*)d_out;

    float *kvlp = nullptr, *headsp = nullptr, *glimpsep = nullptr;
    cudaGetSymbolAddress((void**)&kvlp, g_kvl);
    cudaGetSymbolAddress((void**)&headsp, g_heads);
    cudaGetSymbolAddress((void**)&glimpsep, g_glimpse);

    detect_mask_kernel<<<1, 256>>>((const unsigned int*)mask);

    // kvl = embeddings @ W_kvl   [64000 x 1536], K=512
    {
        dim3 grid(1536 / 128, 64000 / 128);
        gemm_f32<<<grid, 256>>>(emb, Wkvl, kvlp, 64000, 1536, 512);
    }

    // masked multi-head attention -> heads
    {
        dim3 grid(8, 64);
        attn_kernel<<<grid, 640>>>(q, mask);
    }

    // glimpse = heads @ W_out    [1280 x 512], K=512
    {
        dim3 grid(512 / 128, 1280 / 128);
        gemm_f32<<<grid, 256>>>(headsp, Wout, glimpsep, 1280, 512, 512);
    }

    // pointer logits (tanh clip + mask)
    {
        dim3 grid(64, 2, 5);
        pointer_kernel<<<grid, 256>>>(mask);
    }

    // log-softmax + transposed writeout
    {
        dim3 grid(20, 64);
        lsm_kernel<<<grid, 256>>>(out);
    }
}

// round 3
// speedup vs baseline: 2.5686x; 2.5686x over previous
#include <cuda_runtime.h>
#include <cuda_fp16.h>
#include <cstdint>

// B=64, N=1000, D=512, H=8, S=20, DK=64
#define NEG_BIG (-1e9f)
#define INV_SQRT_DK 0.125f
#define INV_SQRT_D 0.04419417382415922f

// ---------------- device scratch ----------------
__device__ __align__(16) float g_kvl[64000 * 1536];
__device__ __align__(16) float g_heads[1280 * 512];
__device__ __align__(16) float g_glimpse[1280 * 512];
__device__ __align__(16) float g_logits[1280 * 1000];
__device__ __align__(16) __half g_Af16[64000 * 512];     // embeddings fp16
__device__ __align__(16) __half g_Wkvl_t[1536 * 512];    // W_kvl^T fp16 [n][k]
__device__ __align__(16) __half g_Wout_t[512 * 512];     // W_out^T fp16 [n][k]
__device__ __align__(16) __half g_Hf16[1280 * 512];      // heads fp16
__device__ int g_mask_mode;

// ---------------- helpers ----------------
__device__ __forceinline__ bool is_feasible(const void* mp, int idx, int mode) {
    if (mode) return ((const unsigned int*)mp)[idx] != 0u;
    return ((const unsigned char*)mp)[idx] != 0;
}
__device__ __forceinline__ float warp_max(float v) {
#pragma unroll
    for (int o = 16; o; o >>= 1) v = fmaxf(v, __shfl_xor_sync(0xffffffffu, v, o));
    return v;
}
__device__ __forceinline__ float warp_sum(float v) {
#pragma unroll
    for (int o = 16; o; o >>= 1) v += __shfl_xor_sync(0xffffffffu, v, o);
    return v;
}
__device__ __forceinline__ uint32_t smem_u32(const void* p) {
    uint32_t a;
    asm("{ .reg .u64 t; cvta.to.shared.u64 t, %1; cvt.u32.u64 %0, t; }" : "=r"(a) : "l"(p));
    return a;
}
__device__ __forceinline__ void cp_async16(uint32_t saddr, const void* gaddr) {
    asm volatile("cp.async.cg.shared.global [%0], [%1], 16;" :: "r"(saddr), "l"(gaddr));
}
__device__ __forceinline__ void cp_commit() { asm volatile("cp.async.commit_group;" ::: "memory"); }
__device__ __forceinline__ void cp_wait1() { asm volatile("cp.async.wait_group 1;" ::: "memory"); }
__device__ __forceinline__ void cp_wait0() { asm volatile("cp.async.wait_group 0;" ::: "memory"); }

__device__ __forceinline__ void ldsm_x4(uint32_t& r0, uint32_t& r1, uint32_t& r2, uint32_t& r3,
                                        uint32_t addr) {
    asm volatile("ldmatrix.sync.aligned.m8n8.x4.shared.b16 {%0,%1,%2,%3}, [%4];"
                 : "=r"(r0), "=r"(r1), "=r"(r2), "=r"(r3) : "r"(addr));
}
__device__ __forceinline__ void mma16816(float& c0, float& c1, float& c2, float& c3,
                                         uint32_t a0, uint32_t a1, uint32_t a2, uint32_t a3,
                                         uint32_t b0, uint32_t b1) {
    asm volatile(
        "mma.sync.aligned.m16n8k16.row.col.f32.f16.f16.f32 "
        "{%0,%1,%2,%3}, {%4,%5,%6,%7}, {%8,%9}, {%0,%1,%2,%3};"
        : "+f"(c0), "+f"(c1), "+f"(c2), "+f"(c3)
        : "r"(a0), "r"(a1), "r"(a2), "r"(a3), "r"(b0), "r"(b1));
}

// ---------------- mask dtype sniffer ----------------
__global__ void detect_mask_kernel(const unsigned int* mw) {
    __shared__ int notI32, notF32;
    if (threadIdx.x == 0) { notI32 = 0; notF32 = 0; }
    __syncthreads();
    int ni = 0, nf = 0;
    for (int i = threadIdx.x; i < 1024; i += 256) {
        unsigned int v = mw[i];
        if (v != 0u && v != 1u) ni = 1;
        if (v != 0u && v != 0x3F800000u) nf = 1;
    }
    if (ni) atomicOr(&notI32, 1);
    if (nf) atomicOr(&notF32, 1);
    __syncthreads();
    if (threadIdx.x == 0) g_mask_mode = (notI32 && notF32) ? 0 : 1;
}

// ---------------- fp32 -> fp16 (contiguous, x4) ----------------
__global__ __launch_bounds__(256)
void conv_f16_kernel(const float* __restrict__ x, __half* __restrict__ y, int n4)
{
    int i = blockIdx.x * 256 + threadIdx.x;
    if (i >= n4) return;
    float4 v = ((const float4*)x)[i];
    __half2 h0 = __floats2half2_rn(v.x, v.y);
    __half2 h1 = __floats2half2_rn(v.z, v.w);
    ((__half2*)y)[i * 2] = h0;
    ((__half2*)y)[i * 2 + 1] = h1;
}

// ---------------- W [512, Nn] -> Wt[Nn][512] fp16 ----------------
__global__ __launch_bounds__(256)
void wtrans_kernel(const float* __restrict__ W, __half* __restrict__ Wt, int Nn)
{
    int idx = blockIdx.x * 256 + threadIdx.x;
    if (idx >= Nn * 512) return;
    int n = idx >> 9;
    int k = idx & 511;
    Wt[idx] = __float2half_rn(W[(size_t)k * Nn + n]);
}

// ---------------- HMMA fp16 GEMM: C[M,Nn] = A[M,512] @ Bt[Nn,512]^T ----------------
// 128x128 tile, BK=64, 3-stage cp.async, 8 warps (each 64x32).
// dynamic smem = 3 * 32768 = 98304 B. grid (Nn/128, M/128), 256 threads.
__global__ __launch_bounds__(256, 1)
void hmma_gemm(const __half* __restrict__ A, const __half* __restrict__ Bt,
               float* __restrict__ C, int Nn)
{
    extern __shared__ char dsm[];
    const uint32_t sb = smem_u32(dsm);
    const int tid = threadIdx.x;
    const int bm = blockIdx.y * 128;
    const int bn = blockIdx.x * 128;
    const int lane = tid & 31, w = tid >> 5;
    const int wr = w >> 2;        // 0..1 : warp m-row (64 rows each)
    const int wc = w & 3;         // 0..3 : warp n-col (32 cols each)

    const char* Ag = (const char*)A + (size_t)bm * 1024;   // 512 halves = 1024 B per row
    const char* Bg = (const char*)Bt + (size_t)bn * 1024;

    // stage layout: A at +0 (16 KB), B at +16384 (16 KB); stride 32768
#define LOAD_CHUNK(kc)                                                      \
    do {                                                                    \
        uint32_t st_ = sb + ((kc) % 3) * 32768;                             \
        size_t gk_ = (size_t)(kc) * 128;                                    \
        _Pragma("unroll")                                                   \
        for (int i_ = 0; i_ < 4; i_++) {                                    \
            int g_ = tid + i_ * 256;                                        \
            int row_ = g_ >> 3, ch_ = g_ & 7;                               \
            uint32_t off_ = row_ * 128 + ch_ * 16;                          \
            uint32_t sw_ = off_ ^ ((off_ >> 3) & 0x70);                     \
            size_t go_ = (size_t)row_ * 1024 + gk_ + ch_ * 16;              \
            cp_async16(st_ + sw_, Ag + go_);                                \
            cp_async16(st_ + 16384 + sw_, Bg + go_);                        \
        }                                                                   \
        cp_commit();                                                        \
    } while (0)

    float acc[4][4][4];
#pragma unroll
    for (int i = 0; i < 4; i++)
#pragma unroll
        for (int j = 0; j < 4; j++)
#pragma unroll
            for (int r = 0; r < 4; r++) acc[i][j][r] = 0.f;

    LOAD_CHUNK(0);
    LOAD_CHUNK(1);

    // precomputed ldmatrix lane-address components
    const int a_row = (lane & 15);              // row within 16-row group
    const int a_c16 = (lane >> 4);              // 0/1 -> +16B (k+8)
    const int b_nrow = (lane & 7) + ((lane >> 4) & 1) * 8;  // n within 16-group
    const int b_c16 = (lane >> 3) & 1;          // 0/1 -> +16B

    for (int kc = 0; kc < 8; ++kc) {
        if (kc == 7) cp_wait0(); else cp_wait1();
        __syncthreads();
        if (kc + 2 < 8) LOAD_CHUNK(kc + 2);

        uint32_t st = sb + (kc % 3) * 32768;
#pragma unroll
        for (int ks = 0; ks < 4; ++ks) {
            uint32_t af[4][4];
#pragma unroll
            for (int mi = 0; mi < 4; ++mi) {
                uint32_t off = (uint32_t)(wr * 64 + mi * 16 + a_row) * 128 + ks * 32 + a_c16 * 16;
                uint32_t sw = off ^ ((off >> 3) & 0x70);
                ldsm_x4(af[mi][0], af[mi][1], af[mi][2], af[mi][3], st + sw);
            }
            uint32_t bf[2][4];
#pragma unroll
            for (int pr = 0; pr < 2; ++pr) {
                uint32_t off = (uint32_t)(wc * 32 + pr * 16 + b_nrow) * 128 + ks * 32 + b_c16 * 16;
                uint32_t sw = off ^ ((off >> 3) & 0x70);
                ldsm_x4(bf[pr][0], bf[pr][1], bf[pr][2], bf[pr][3], st + 16384 + sw);
            }
#pragma unroll
            for (int mi = 0; mi < 4; ++mi) {
#pragma unroll
                for (int pr = 0; pr < 2; ++pr) {
                    mma16816(acc[mi][pr * 2][0], acc[mi][pr * 2][1],
                             acc[mi][pr * 2][2], acc[mi][pr * 2][3],
                             af[mi][0], af[mi][1], af[mi][2], af[mi][3],
                             bf[pr][0], bf[pr][1]);
                    mma16816(acc[mi][pr * 2 + 1][0], acc[mi][pr * 2 + 1][1],
                             acc[mi][pr * 2 + 1][2], acc[mi][pr * 2 + 1][3],
                             af[mi][0], af[mi][1], af[mi][2], af[mi][3],
                             bf[pr][2], bf[pr][3]);
                }
            }
        }
        __syncthreads();
    }

    // epilogue: direct float2 stores
#pragma unroll
    for (int mi = 0; mi < 4; ++mi) {
        int row0 = bm + wr * 64 + mi * 16 + (lane >> 2);
#pragma unroll
        for (int ni = 0; ni < 4; ++ni) {
            int col = bn + wc * 32 + ni * 8 + (lane & 3) * 2;
            *(float2*)(C + (size_t)row0 * Nn + col) = make_float2(acc[mi][ni][0], acc[mi][ni][1]);
            *(float2*)(C + (size_t)(row0 + 8) * Nn + col) = make_float2(acc[mi][ni][2], acc[mi][ni][3]);
        }
    }
#undef LOAD_CHUNK
}

// ---------------- flash-style masked MHA ----------------
__global__ __launch_bounds__(640)
void attn_kernel(const float* __restrict__ qin, const void* __restrict__ mask)
{
    __shared__ __align__(16) float sq[20][64];
    __shared__ __align__(16) float sk[40][64];
    __shared__ __align__(16) float sv[40][64];
    const int h = blockIdx.x, b = blockIdx.y;
    const int tid = threadIdx.x;
    const int mode = g_mask_mode;

    if (tid < 320) {
        int s = tid >> 4, dg = (tid & 15) << 2;
        *(float4*)&sq[s][dg] = *(const float4*)(qin + (size_t)(b * 20 + s) * 512 + h * 64 + dg);
    }

    const int lane = tid & 31, w = tid >> 5;
    float m = -1e30f, l = 0.f, acc0 = 0.f, acc1 = 0.f;
    float q0 = 0.f, q1 = 0.f;

    const int nn = tid >> 4;
    const int dg = (tid & 15) << 2;

    for (int t = 0; t < 25; ++t) {
        const int n0 = t * 40;
        __syncthreads();
        {
            const float* base = g_kvl + (size_t)(b * 1000 + n0 + nn) * 1536 + h * 64 + dg;
            *(float4*)&sk[nn][dg] = *(const float4*)(base);
            *(float4*)&sv[nn][dg] = *(const float4*)(base + 512);
        }
        __syncthreads();
        if (w < 20) {
            if (t == 0) { q0 = sq[w][lane]; q1 = sq[w][lane + 32]; }
            const int midx0 = (b * 20 + w) * 1000 + n0;
#pragma unroll 4
            for (int n = 0; n < 40; ++n) {
                float x = q0 * sk[n][lane] + q1 * sk[n][lane + 32];
                x += __shfl_xor_sync(0xffffffffu, x, 16);
                x += __shfl_xor_sync(0xffffffffu, x, 8);
                x += __shfl_xor_sync(0xffffffffu, x, 4);
                x += __shfl_xor_sync(0xffffffffu, x, 2);
                x += __shfl_xor_sync(0xffffffffu, x, 1);
                x *= INV_SQRT_DK;
                if (is_feasible(mask, midx0 + n, mode)) {
                    float mn = fmaxf(m, x);
                    float corr = __expf(m - mn);
                    float p = __expf(x - mn);
                    l = l * corr + p;
                    acc0 = acc0 * corr + p * sv[n][lane];
                    acc1 = acc1 * corr + p * sv[n][lane + 32];
                    m = mn;
                }
            }
        }
    }
    if (w < 20) {
        float inv = 1.f / l;
        size_t o = (size_t)(b * 20 + w) * 512 + h * 64 + lane;
        g_heads[o] = acc0 * inv;
        g_heads[o + 32] = acc1 * inv;
    }
}

// ---------------- pointer logits ----------------
__global__ __launch_bounds__(256)
void pointer_kernel(const void* __restrict__ mask)
{
    __shared__ __align__(16) float sg[10 * 512];
    __shared__ __align__(16) float slk[8 * 512];
    const int b = blockIdx.x;
    const int sbase = blockIdx.y * 10;
    const int nsl = blockIdx.z;
    const int tid = threadIdx.x;
    const int mode = g_mask_mode;

    for (int i = tid; i < 10 * 512 / 4; i += 256) {
        int off = i << 2;
        int s = off >> 9, d = off & 511;
        *(float4*)&sg[off] = *(const float4*)(g_glimpse + (size_t)(b * 20 + sbase + s) * 512 + d);
    }

    const int lane = tid & 31, w = tid >> 5;
    for (int t = 0; t < 25; ++t) {
        const int n0 = nsl * 200 + t * 8;
        __syncthreads();
        for (int i = tid; i < 8 * 512 / 4; i += 256) {
            int off = i << 2;
            int nn = off >> 9, d = off & 511;
            *(float4*)&slk[off] = *(const float4*)(g_kvl + (size_t)(b * 1000 + n0 + nn) * 1536 + 1024 + d);
        }
        __syncthreads();
#pragma unroll
        for (int pp = 0; pp < 10; ++pp) {
            const int p = w * 10 + pp;
            const int sl = p >> 3, n = p & 7;
            const float* gr = &sg[sl * 512];
            const float* kr = &slk[n * 512];
            float sum = 0.f;
#pragma unroll
            for (int i = 0; i < 16; ++i)
                sum += gr[lane + i * 32] * kr[lane + i * 32];
            sum = warp_sum(sum);
            if (lane == 0) {
                float lg = 10.f * tanhf(sum * INV_SQRT_D);
                int gidx = (b * 20 + sbase + sl) * 1000 + n0 + n;
                if (!is_feasible(mask, gidx, mode)) lg = NEG_BIG;
                g_logits[gidx] = lg;
            }
        }
    }
}

// ---------------- log-softmax + transposed writeout ----------------
__global__ __launch_bounds__(256)
void lsm_kernel(float* __restrict__ out)
{
    const int s = blockIdx.x, b = blockIdx.y;
    const float* row = g_logits + (size_t)(b * 20 + s) * 1000;
    float* orow = out + (size_t)(s * 64 + b) * 1000;
    __shared__ float red[8];
    const int tid = threadIdx.x;
    const int lane = tid & 31, w = tid >> 5;

    float mx = -1e30f;
    for (int i = tid; i < 1000; i += 256) mx = fmaxf(mx, row[i]);
    mx = warp_max(mx);
    if (lane == 0) red[w] = mx;
    __syncthreads();
    if (w == 0) {
        float v = (lane < 8) ? red[lane] : -1e30f;
        v = warp_max(v);
        if (lane == 0) red[0] = v;
    }
    __syncthreads();
    mx = red[0];
    __syncthreads();

    float se = 0.f;
    for (int i = tid; i < 1000; i += 256) se += __expf(row[i] - mx);
    se = warp_sum(se);
    if (lane == 0) red[w] = se;
    __syncthreads();
    if (w == 0) {
        float v = (lane < 8) ? red[lane] : 0.f;
        v = warp_sum(v);
        if (lane == 0) red[0] = v;
    }
    __syncthreads();
    const float lse = mx + logf(red[0]);

    for (int i = tid; i < 1000; i += 256) orow[i] = row[i] - lse;
}

// ---------------- launch ----------------
extern "C" void kernel_launch(void* const* d_in, const int* in_sizes, int n_in,
                              void* d_out, int out_size)
{
    (void)out_size;
    const float* emb = nullptr;
    const float* q = nullptr;
    const void* mask = nullptr;
    const float* Wkvl = nullptr;
    const float* Wout = nullptr;
    for (int i = 0; i < n_in; ++i) {
        switch (in_sizes[i]) {
            case 32768000: emb = (const float*)d_in[i]; break;
            case 655360:   q = (const float*)d_in[i]; break;
            case 1280000:  mask = d_in[i]; break;
            case 786432:   Wkvl = (const float*)d_in[i]; break;
            case 262144:   Wout = (const float*)d_in[i]; break;
            default: break;
        }
    }
    float* out = (float*)d_out;

    float *kvlp, *headsp, *glimpsep;
    __half *af16, *wkt, *wot, *hf16;
    cudaGetSymbolAddress((void**)&kvlp, g_kvl);
    cudaGetSymbolAddress((void**)&headsp, g_heads);
    cudaGetSymbolAddress((void**)&glimpsep, g_glimpse);
    cudaGetSymbolAddress((void**)&af16, g_Af16);
    cudaGetSymbolAddress((void**)&wkt, g_Wkvl_t);
    cudaGetSymbolAddress((void**)&wot, g_Wout_t);
    cudaGetSymbolAddress((void**)&hf16, g_Hf16);

    cudaFuncSetAttribute(hmma_gemm, cudaFuncAttributeMaxDynamicSharedMemorySize, 98304);

    detect_mask_kernel<<<1, 256>>>((const unsigned int*)mask);

    // conversions
    conv_f16_kernel<<<32000, 256>>>(emb, af16, 8192000);
    wtrans_kernel<<<3072, 256>>>(Wkvl, wkt, 1536);
    wtrans_kernel<<<1024, 256>>>(Wout, wot, 512);

    // kvl = embeddings @ W_kvl  [64000 x 1536]
    {
        dim3 grid(12, 500);
        hmma_gemm<<<grid, 256, 98304>>>(af16, wkt, kvlp, 1536);
    }

    // masked multi-head attention
    {
        dim3 grid(8, 64);
        attn_kernel<<<grid, 640>>>(q, mask);
    }

    // glimpse = heads @ W_out  [1280 x 512]
    conv_f16_kernel<<<640, 256>>>(headsp, hf16, 163840);
    {
        dim3 grid(4, 10);
        hmma_gemm<<<grid, 256, 98304>>>(hf16, wot, glimpsep, 512);
    }

    // pointer logits
    {
        dim3 grid(64, 2, 5);
        pointer_kernel<<<grid, 256>>>(mask);
    }

    // log-softmax
    {
        dim3 grid(20, 64);
        lsm_kernel<<<grid, 256>>>(out);
    }
}

// round 4
// speedup vs baseline: 2.9295x; 1.1405x over previous
#include <cuda_runtime.h>
#include <cuda_fp16.h>
#include <cstdint>

// B=64, N=1000, D=512, H=8, S=20, DK=64
#define NEG_BIG (-1e9f)
#define INV_SQRT_DK 0.125f
#define INV_SQRT_D 0.04419417382415922f

// ---------------- device scratch ----------------
__device__ __align__(16) __half g_kvlh[64000 * 1536];    // fp16 [b*1000+n][gk|gv|lk]
__device__ __align__(16) float g_heads[1280 * 512];
__device__ __align__(16) float g_glimpse[1280 * 512];
__device__ __align__(16) float g_logits[1280 * 1000];
__device__ __align__(16) __half g_Af16[64000 * 512];
__device__ __align__(16) __half g_Wkvl_t[1536 * 512];
__device__ __align__(16) __half g_Wout_t[512 * 512];
__device__ __align__(16) __half g_Hf16[1280 * 512];
__device__ int g_mask_mode;

// ---------------- helpers ----------------
__device__ __forceinline__ bool is_feasible(const void* mp, int idx, int mode) {
    if (mode) return ((const unsigned int*)mp)[idx] != 0u;
    return ((const unsigned char*)mp)[idx] != 0;
}
__device__ __forceinline__ float warp_max(float v) {
#pragma unroll
    for (int o = 16; o; o >>= 1) v = fmaxf(v, __shfl_xor_sync(0xffffffffu, v, o));
    return v;
}
__device__ __forceinline__ float warp_sum(float v) {
#pragma unroll
    for (int o = 16; o; o >>= 1) v += __shfl_xor_sync(0xffffffffu, v, o);
    return v;
}
__device__ __forceinline__ uint32_t smem_u32(const void* p) {
    uint32_t a;
    asm("{ .reg .u64 t; cvta.to.shared.u64 t, %1; cvt.u32.u64 %0, t; }" : "=r"(a) : "l"(p));
    return a;
}
__device__ __forceinline__ void cp_async16(uint32_t saddr, const void* gaddr) {
    asm volatile("cp.async.cg.shared.global [%0], [%1], 16;" :: "r"(saddr), "l"(gaddr));
}
__device__ __forceinline__ void cp_commit() { asm volatile("cp.async.commit_group;" ::: "memory"); }
__device__ __forceinline__ void cp_wait1() { asm volatile("cp.async.wait_group 1;" ::: "memory"); }
__device__ __forceinline__ void cp_wait0() { asm volatile("cp.async.wait_group 0;" ::: "memory"); }

__device__ __forceinline__ void ldsm_x4(uint32_t& r0, uint32_t& r1, uint32_t& r2, uint32_t& r3,
                                        uint32_t addr) {
    asm volatile("ldmatrix.sync.aligned.m8n8.x4.shared.b16 {%0,%1,%2,%3}, [%4];"
                 : "=r"(r0), "=r"(r1), "=r"(r2), "=r"(r3) : "r"(addr));
}
__device__ __forceinline__ void mma16816(float& c0, float& c1, float& c2, float& c3,
                                         uint32_t a0, uint32_t a1, uint32_t a2, uint32_t a3,
                                         uint32_t b0, uint32_t b1) {
    asm volatile(
        "mma.sync.aligned.m16n8k16.row.col.f32.f16.f16.f32 "
        "{%0,%1,%2,%3}, {%4,%5,%6,%7}, {%8,%9}, {%0,%1,%2,%3};"
        : "+f"(c0), "+f"(c1), "+f"(c2), "+f"(c3)
        : "r"(a0), "r"(a1), "r"(a2), "r"(a3), "r"(b0), "r"(b1));
}

// ---------------- mask dtype sniffer ----------------
__global__ void detect_mask_kernel(const unsigned int* mw) {
    __shared__ int notI32, notF32;
    if (threadIdx.x == 0) { notI32 = 0; notF32 = 0; }
    __syncthreads();
    int ni = 0, nf = 0;
    for (int i = threadIdx.x; i < 1024; i += 256) {
        unsigned int v = mw[i];
        if (v != 0u && v != 1u) ni = 1;
        if (v != 0u && v != 0x3F800000u) nf = 1;
    }
    if (ni) atomicOr(&notI32, 1);
    if (nf) atomicOr(&notF32, 1);
    __syncthreads();
    if (threadIdx.x == 0) g_mask_mode = (notI32 && notF32) ? 0 : 1;
}

// ---------------- fp32 -> fp16 ----------------
__global__ __launch_bounds__(256)
void conv_f16_kernel(const float* __restrict__ x, __half* __restrict__ y, int n4)
{
    int i = blockIdx.x * 256 + threadIdx.x;
    if (i >= n4) return;
    float4 v = ((const float4*)x)[i];
    ((__half2*)y)[i * 2] = __floats2half2_rn(v.x, v.y);
    ((__half2*)y)[i * 2 + 1] = __floats2half2_rn(v.z, v.w);
}

// ---------------- W [512, Nn] -> Wt[Nn][512] fp16 ----------------
__global__ __launch_bounds__(256)
void wtrans_kernel(const float* __restrict__ W, __half* __restrict__ Wt, int Nn)
{
    int idx = blockIdx.x * 256 + threadIdx.x;
    if (idx >= Nn * 512) return;
    int n = idx >> 9;
    int k = idx & 511;
    Wt[idx] = __float2half_rn(W[(size_t)k * Nn + n]);
}

// ---------------- HMMA fp16 GEMM, templated output ----------------
// C[M,Nn] = A[M,512] @ Bt[Nn,512]^T. 128x128 tile, BK=64, 2-stage cp.async,
// 8 warps (64x32 each). smem = 2*32768 = 65536. 2 CTAs/SM.
template <bool HALF_OUT>
__global__ __launch_bounds__(256, 2)
void hmma_gemm(const __half* __restrict__ A, const __half* __restrict__ Bt,
               void* __restrict__ Cv, int Nn)
{
    extern __shared__ char dsm[];
    const uint32_t sb = smem_u32(dsm);
    const int tid = threadIdx.x;
    const int bm = blockIdx.y * 128;
    const int bn = blockIdx.x * 128;
    const int lane = tid & 31, w = tid >> 5;
    const int wr = w >> 2;
    const int wc = w & 3;

    const char* Ag = (const char*)A + (size_t)bm * 1024;
    const char* Bg = (const char*)Bt + (size_t)bn * 1024;

#define LOAD_CHUNK(kc)                                                      \
    do {                                                                    \
        uint32_t st_ = sb + ((kc) & 1) * 32768;                             \
        size_t gk_ = (size_t)(kc) * 128;                                    \
        _Pragma("unroll")                                                   \
        for (int i_ = 0; i_ < 4; i_++) {                                    \
            int g_ = tid + i_ * 256;                                        \
            int row_ = g_ >> 3, ch_ = g_ & 7;                               \
            uint32_t off_ = row_ * 128 + ch_ * 16;                          \
            uint32_t sw_ = off_ ^ ((off_ >> 3) & 0x70);                     \
            size_t go_ = (size_t)row_ * 1024 + gk_ + ch_ * 16;              \
            cp_async16(st_ + sw_, Ag + go_);                                \
            cp_async16(st_ + 16384 + sw_, Bg + go_);                        \
        }                                                                   \
        cp_commit();                                                        \
    } while (0)

    float acc[4][4][4];
#pragma unroll
    for (int i = 0; i < 4; i++)
#pragma unroll
        for (int j = 0; j < 4; j++)
#pragma unroll
            for (int r = 0; r < 4; r++) acc[i][j][r] = 0.f;

    LOAD_CHUNK(0);

    const int a_row = (lane & 15);
    const int a_c16 = (lane >> 4);
    const int b_nrow = (lane & 7) + ((lane >> 4) & 1) * 8;
    const int b_c16 = (lane >> 3) & 1;

    for (int kc = 0; kc < 8; ++kc) {
        if (kc + 1 < 8) { LOAD_CHUNK(kc + 1); cp_wait1(); } else { cp_wait0(); }
        __syncthreads();

        uint32_t st = sb + (kc & 1) * 32768;
#pragma unroll
        for (int ks = 0; ks < 4; ++ks) {
            uint32_t af[4][4];
#pragma unroll
            for (int mi = 0; mi < 4; ++mi) {
                uint32_t off = (uint32_t)(wr * 64 + mi * 16 + a_row) * 128 + ks * 32 + a_c16 * 16;
                uint32_t sw = off ^ ((off >> 3) & 0x70);
                ldsm_x4(af[mi][0], af[mi][1], af[mi][2], af[mi][3], st + sw);
            }
            uint32_t bf[2][4];
#pragma unroll
            for (int pr = 0; pr < 2; ++pr) {
                uint32_t off = (uint32_t)(wc * 32 + pr * 16 + b_nrow) * 128 + ks * 32 + b_c16 * 16;
                uint32_t sw = off ^ ((off >> 3) & 0x70);
                ldsm_x4(bf[pr][0], bf[pr][1], bf[pr][2], bf[pr][3], st + 16384 + sw);
            }
#pragma unroll
            for (int mi = 0; mi < 4; ++mi) {
#pragma unroll
                for (int pr = 0; pr < 2; ++pr) {
                    mma16816(acc[mi][pr * 2][0], acc[mi][pr * 2][1],
                             acc[mi][pr * 2][2], acc[mi][pr * 2][3],
                             af[mi][0], af[mi][1], af[mi][2], af[mi][3],
                             bf[pr][0], bf[pr][1]);
                    mma16816(acc[mi][pr * 2 + 1][0], acc[mi][pr * 2 + 1][1],
                             acc[mi][pr * 2 + 1][2], acc[mi][pr * 2 + 1][3],
                             af[mi][0], af[mi][1], af[mi][2], af[mi][3],
                             bf[pr][2], bf[pr][3]);
                }
            }
        }
        __syncthreads();
    }

#pragma unroll
    for (int mi = 0; mi < 4; ++mi) {
        int row0 = bm + wr * 64 + mi * 16 + (lane >> 2);
#pragma unroll
        for (int ni = 0; ni < 4; ++ni) {
            int col = bn + wc * 32 + ni * 8 + (lane & 3) * 2;
            if (HALF_OUT) {
                __half* C = (__half*)Cv;
                *(__half2*)(C + (size_t)row0 * Nn + col) =
                    __floats2half2_rn(acc[mi][ni][0], acc[mi][ni][1]);
                *(__half2*)(C + (size_t)(row0 + 8) * Nn + col) =
                    __floats2half2_rn(acc[mi][ni][2], acc[mi][ni][3]);
            } else {
                float* C = (float*)Cv;
                *(float2*)(C + (size_t)row0 * Nn + col) = make_float2(acc[mi][ni][0], acc[mi][ni][1]);
                *(float2*)(C + (size_t)(row0 + 8) * Nn + col) = make_float2(acc[mi][ni][2], acc[mi][ni][3]);
            }
        }
    }
#undef LOAD_CHUNK
}

// ---------------- flash-style masked MHA (reads fp16 kvl) ----------------
__global__ __launch_bounds__(640)
void attn_kernel(const float* __restrict__ qin, const void* __restrict__ mask)
{
    __shared__ __align__(16) float sq[20][64];
    __shared__ __align__(16) float sk[40][64];
    __shared__ __align__(16) float sv[40][64];
    const int h = blockIdx.x, b = blockIdx.y;
    const int tid = threadIdx.x;
    const int mode = g_mask_mode;

    if (tid < 320) {
        int s = tid >> 4, dg = (tid & 15) << 2;
        *(float4*)&sq[s][dg] = *(const float4*)(qin + (size_t)(b * 20 + s) * 512 + h * 64 + dg);
    }

    const int lane = tid & 31, w = tid >> 5;
    float m = -1e30f, l = 0.f, acc0 = 0.f, acc1 = 0.f;
    float q0 = 0.f, q1 = 0.f;

    const int nn = tid >> 4;
    const int dg = (tid & 15) << 2;

    for (int t = 0; t < 25; ++t) {
        const int n0 = t * 40;
        __syncthreads();
        {
            const __half* base = g_kvlh + (size_t)(b * 1000 + n0 + nn) * 1536 + h * 64 + dg;
            __half2 k01 = *(const __half2*)(base);
            __half2 k23 = *(const __half2*)(base + 2);
            __half2 v01 = *(const __half2*)(base + 512);
            __half2 v23 = *(const __half2*)(base + 514);
            float2 kf0 = __half22float2(k01), kf1 = __half22float2(k23);
            float2 vf0 = __half22float2(v01), vf1 = __half22float2(v23);
            *(float4*)&sk[nn][dg] = make_float4(kf0.x, kf0.y, kf1.x, kf1.y);
            *(float4*)&sv[nn][dg] = make_float4(vf0.x, vf0.y, vf1.x, vf1.y);
        }
        __syncthreads();
        if (w < 20) {
            if (t == 0) { q0 = sq[w][lane]; q1 = sq[w][lane + 32]; }
            const int midx0 = (b * 20 + w) * 1000 + n0;
#pragma unroll 4
            for (int n = 0; n < 40; ++n) {
                float x = q0 * sk[n][lane] + q1 * sk[n][lane + 32];
                x += __shfl_xor_sync(0xffffffffu, x, 16);
                x += __shfl_xor_sync(0xffffffffu, x, 8);
                x += __shfl_xor_sync(0xffffffffu, x, 4);
                x += __shfl_xor_sync(0xffffffffu, x, 2);
                x += __shfl_xor_sync(0xffffffffu, x, 1);
                x *= INV_SQRT_DK;
                if (is_feasible(mask, midx0 + n, mode)) {
                    float mn = fmaxf(m, x);
                    float corr = __expf(m - mn);
                    float p = __expf(x - mn);
                    l = l * corr + p;
                    acc0 = acc0 * corr + p * sv[n][lane];
                    acc1 = acc1 * corr + p * sv[n][lane + 32];
                    m = mn;
                }
            }
        }
    }
    if (w < 20) {
        float inv = 1.f / l;
        size_t o = (size_t)(b * 20 + w) * 512 + h * 64 + lane;
        g_heads[o] = acc0 * inv;
        g_heads[o + 32] = acc1 * inv;
    }
}

// ---------------- pointer logits (reads fp16 logit_k) ----------------
__global__ __launch_bounds__(256)
void pointer_kernel(const void* __restrict__ mask)
{
    __shared__ __align__(16) float sg[10 * 512];
    __shared__ __align__(16) float slk[8 * 512];
    const int b = blockIdx.x;
    const int sbase = blockIdx.y * 10;
    const int nsl = blockIdx.z;
    const int tid = threadIdx.x;
    const int mode = g_mask_mode;

    for (int i = tid; i < 10 * 512 / 4; i += 256) {
        int off = i << 2;
        int s = off >> 9, d = off & 511;
        *(float4*)&sg[off] = *(const float4*)(g_glimpse + (size_t)(b * 20 + sbase + s) * 512 + d);
    }

    const int lane = tid & 31, w = tid >> 5;
    for (int t = 0; t < 25; ++t) {
        const int n0 = nsl * 200 + t * 8;
        __syncthreads();
        for (int i = tid; i < 8 * 512 / 8; i += 256) {
            int off = i << 3;
            int nn = off >> 9, d = off & 511;
            const __half* src = g_kvlh + (size_t)(b * 1000 + n0 + nn) * 1536 + 1024 + d;
            uint4 raw = *(const uint4*)src;
            const __half2* hp = (const __half2*)&raw;
            float2 f0 = __half22float2(hp[0]);
            float2 f1 = __half22float2(hp[1]);
            float2 f2 = __half22float2(hp[2]);
            float2 f3 = __half22float2(hp[3]);
            *(float4*)&slk[off] = make_float4(f0.x, f0.y, f1.x, f1.y);
            *(float4*)&slk[off + 4] = make_float4(f2.x, f2.y, f3.x, f3.y);
        }
        __syncthreads();
#pragma unroll
        for (int pp = 0; pp < 10; ++pp) {
            const int p = w * 10 + pp;
            const int sl = p >> 3, n = p & 7;
            const float* gr = &sg[sl * 512];
            const float* kr = &slk[n * 512];
            float sum = 0.f;
#pragma unroll
            for (int i = 0; i < 16; ++i)
                sum += gr[lane + i * 32] * kr[lane + i * 32];
            sum = warp_sum(sum);
            if (lane == 0) {
                float lg = 10.f * tanhf(sum * INV_SQRT_D);
                int gidx = (b * 20 + sbase + sl) * 1000 + n0 + n;
                if (!is_feasible(mask, gidx, mode)) lg = NEG_BIG;
                g_logits[gidx] = lg;
            }
        }
    }
}

// ---------------- log-softmax + transposed writeout ----------------
__global__ __launch_bounds__(256)
void lsm_kernel(float* __restrict__ out)
{
    const int s = blockIdx.x, b = blockIdx.y;
    const float* row = g_logits + (size_t)(b * 20 + s) * 1000;
    float* orow = out + (size_t)(s * 64 + b) * 1000;
    __shared__ float red[8];
    const int tid = threadIdx.x;
    const int lane = tid & 31, w = tid >> 5;

    float mx = -1e30f;
    for (int i = tid; i < 1000; i += 256) mx = fmaxf(mx, row[i]);
    mx = warp_max(mx);
    if (lane == 0) red[w] = mx;
    __syncthreads();
    if (w == 0) {
        float v = (lane < 8) ? red[lane] : -1e30f;
        v = warp_max(v);
        if (lane == 0) red[0] = v;
    }
    __syncthreads();
    mx = red[0];
    __syncthreads();

    float se = 0.f;
    for (int i = tid; i < 1000; i += 256) se += __expf(row[i] - mx);
    se = warp_sum(se);
    if (lane == 0) red[w] = se;
    __syncthreads();
    if (w == 0) {
        float v = (lane < 8) ? red[lane] : 0.f;
        v = warp_sum(v);
        if (lane == 0) red[0] = v;
    }
    __syncthreads();
    const float lse = mx + logf(red[0]);

    for (int i = tid; i < 1000; i += 256) orow[i] = row[i] - lse;
}

// ---------------- launch ----------------
extern "C" void kernel_launch(void* const* d_in, const int* in_sizes, int n_in,
                              void* d_out, int out_size)
{
    (void)out_size;
    const float* emb = nullptr;
    const float* q = nullptr;
    const void* mask = nullptr;
    const float* Wkvl = nullptr;
    const float* Wout = nullptr;
    for (int i = 0; i < n_in; ++i) {
        switch (in_sizes[i]) {
            case 32768000: emb = (const float*)d_in[i]; break;
            case 655360:   q = (const float*)d_in[i]; break;
            case 1280000:  mask = d_in[i]; break;
            case 786432:   Wkvl = (const float*)d_in[i]; break;
            case 262144:   Wout = (const float*)d_in[i]; break;
            default: break;
        }
    }
    float* out = (float*)d_out;

    float *headsp, *glimpsep;
    __half *kvlhp, *af16, *wkt, *wot, *hf16;
    cudaGetSymbolAddress((void**)&kvlhp, g_kvlh);
    cudaGetSymbolAddress((void**)&headsp, g_heads);
    cudaGetSymbolAddress((void**)&glimpsep, g_glimpse);
    cudaGetSymbolAddress((void**)&af16, g_Af16);
    cudaGetSymbolAddress((void**)&wkt, g_Wkvl_t);
    cudaGetSymbolAddress((void**)&wot, g_Wout_t);
    cudaGetSymbolAddress((void**)&hf16, g_Hf16);

    cudaFuncSetAttribute(hmma_gemm<true>, cudaFuncAttributeMaxDynamicSharedMemorySize, 65536);
    cudaFuncSetAttribute(hmma_gemm<false>, cudaFuncAttributeMaxDynamicSharedMemorySize, 65536);

    detect_mask_kernel<<<1, 256>>>((const unsigned int*)mask);

    conv_f16_kernel<<<32000, 256>>>(emb, af16, 8192000);
    wtrans_kernel<<<3072, 256>>>(Wkvl, wkt, 1536);
    wtrans_kernel<<<1024, 256>>>(Wout, wot, 512);

    // kvl = embeddings @ W_kvl  [64000 x 1536] -> fp16
    {
        dim3 grid(12, 500);
        hmma_gemm<true><<<grid, 256, 65536>>>(af16, wkt, kvlhp, 1536);
    }

    // attention
    {
        dim3 grid(8, 64);
        attn_kernel<<<grid, 640>>>(q, mask);
    }

    // glimpse = heads @ W_out  [1280 x 512] -> fp32
    conv_f16_kernel<<<640, 256>>>(headsp, hf16, 163840);
    {
        dim3 grid(4, 10);
        hmma_gemm<false><<<grid, 256, 65536>>>(hf16, wot, glimpsep, 512);
    }

    // pointer logits
    {
        dim3 grid(64, 2, 5);
        pointer_kernel<<<grid, 256>>>(mask);
    }

    // log-softmax
    {
        dim3 grid(20, 64);
        lsm_kernel<<<grid, 256>>>(out);
    }
}